// round 6
// baseline (speedup 1.0000x reference)
#include <cuda_runtime.h>
#include <cuda_fp16.h>
#include <cuda_bf16.h>
#include <math.h>

#define NN 50000
#define EE 1600000
#define DIM 128
#define HEADS 4
#define ODIM 32
#define ALPHA 0.2f
#define WPB 8

// ---------------- device scratch ----------------
__device__ __align__(16) float  g_H[NN * DIM];     // fp32 features (scores path)
__device__ __align__(16) __half g_Hh[NN * DIM];    // fp16 features (gather path)
__device__ __align__(16) float  g_Hs[NN * HEADS];
__device__ __align__(16) float  g_Ht[NN * HEADS];
__device__ int g_cnt[NN];
__device__ int g_off[NN + 1];
__device__ int g_cur[NN];
__device__ int g_csr[EE];
__device__ unsigned g_maxenc;

__device__ __forceinline__ unsigned enc_f(float f) {
    unsigned u = __float_as_uint(f);
    return (u & 0x80000000u) ? ~u : (u | 0x80000000u);
}
__device__ __forceinline__ float dec_f(unsigned u) {
    return (u & 0x80000000u) ? __uint_as_float(u ^ 0x80000000u)
                             : __uint_as_float(~u);
}
__device__ __forceinline__ float lrelu(float x) { return x > 0.f ? x : ALPHA * x; }

// ---------------- K0: init ----------------
__global__ void init_kernel() {
    int i = blockIdx.x * blockDim.x + threadIdx.x;
    if (i == 0) g_maxenc = 0u;
    if (i < NN) g_cnt[i] = 0;
}

// ---------------- K1: tensor-core GEMM (bf16 split, 3 products) ----------------
// Block: 64 rows x 128 cols. 8 warps: wr=warp>>1 row group (16 rows), wc=warp&1 col half (64).
#define BSTRIDE 72   // bf16 elems per n-row in smem: bank = (4n + tig) mod 32, conflict-free

__device__ __forceinline__ void split_pack(float2 f, unsigned& hi, unsigned& lo) {
    __nv_bfloat16 h0 = __float2bfloat16(f.x);
    __nv_bfloat16 h1 = __float2bfloat16(f.y);
    float r0 = f.x - __bfloat162float(h0);
    float r1 = f.y - __bfloat162float(h1);
    __nv_bfloat162 hv = __halves2bfloat162(h0, h1);
    __nv_bfloat162 lv = __halves2bfloat162(__float2bfloat16(r0), __float2bfloat16(r1));
    hi = *(unsigned*)&hv;
    lo = *(unsigned*)&lv;
}

__device__ __forceinline__ void mma_bf16(float* c, const unsigned* a, unsigned b0, unsigned b1) {
    asm volatile(
        "mma.sync.aligned.m16n8k16.row.col.f32.bf16.bf16.f32 "
        "{%0,%1,%2,%3}, {%4,%5,%6,%7}, {%8,%9}, {%0,%1,%2,%3};\n"
        : "+f"(c[0]), "+f"(c[1]), "+f"(c[2]), "+f"(c[3])
        : "r"(a[0]), "r"(a[1]), "r"(a[2]), "r"(a[3]), "r"(b0), "r"(b1));
}

__global__ __launch_bounds__(256) void gemm_tc(const float* __restrict__ X,
                                               const float* __restrict__ W) {
    __shared__ __align__(16) __nv_bfloat16 Bs[2][128 * BSTRIDE]; // [hi/lo][n*BSTRIDE + klocal]
    const int tid  = threadIdx.x;
    const int lane = tid & 31;
    const int warp = tid >> 5;
    const int wr = warp >> 1;
    const int wc = warp & 1;
    const int g   = lane >> 2;   // groupID 0-7
    const int tig = lane & 3;    // thread-in-group
    const int m0 = blockIdx.x * 64;

    float c[8][4];
#pragma unroll
    for (int i = 0; i < 8; i++)
#pragma unroll
        for (int j = 0; j < 4; j++) c[i][j] = 0.f;

    const int r0 = m0 + wr * 16 + g;
    const int r1 = r0 + 8;
    const bool v0 = (r0 < NN), v1 = (r1 < NN);

    for (int ks = 0; ks < 2; ks++) {
        __syncthreads();
        // stage W[k = 64ks..64ks+63][n] -> Bs[n][klocal], split hi/lo
        for (int idx = tid; idx < 64 * 128; idx += 256) {
            int kl = idx & 63;
            int n  = idx >> 6;
            float w = W[(size_t)(ks * 64 + kl) * DIM + n];
            __nv_bfloat16 h = __float2bfloat16(w);
            float rl = w - __bfloat162float(h);
            Bs[0][n * BSTRIDE + kl] = h;
            Bs[1][n * BSTRIDE + kl] = __float2bfloat16(rl);
        }
        __syncthreads();

#pragma unroll
        for (int kl = 0; kl < 4; kl++) {
            const int k0 = ks * 64 + kl * 16;
            // A fragment loads (row-major, k pairs at tig*2 and tig*2+8)
            float2 z = make_float2(0.f, 0.f);
            float2 x00 = v0 ? *(const float2*)(X + (size_t)r0 * DIM + k0 + tig * 2)     : z;
            float2 x10 = v1 ? *(const float2*)(X + (size_t)r1 * DIM + k0 + tig * 2)     : z;
            float2 x01 = v0 ? *(const float2*)(X + (size_t)r0 * DIM + k0 + 8 + tig * 2) : z;
            float2 x11 = v1 ? *(const float2*)(X + (size_t)r1 * DIM + k0 + 8 + tig * 2) : z;
            unsigned a_hi[4], a_lo[4];
            split_pack(x00, a_hi[0], a_lo[0]);
            split_pack(x10, a_hi[1], a_lo[1]);
            split_pack(x01, a_hi[2], a_lo[2]);
            split_pack(x11, a_hi[3], a_lo[3]);

            const int klocal = kl * 16 + tig * 2;
#pragma unroll
            for (int nt = 0; nt < 8; nt++) {
                int n = wc * 64 + nt * 8 + g;
                unsigned bh0 = *(const unsigned*)&Bs[0][n * BSTRIDE + klocal];
                unsigned bh1 = *(const unsigned*)&Bs[0][n * BSTRIDE + klocal + 8];
                unsigned bl0 = *(const unsigned*)&Bs[1][n * BSTRIDE + klocal];
                unsigned bl1 = *(const unsigned*)&Bs[1][n * BSTRIDE + klocal + 8];
                mma_bf16(c[nt], a_hi, bh0, bh1);
                mma_bf16(c[nt], a_hi, bl0, bl1);
                mma_bf16(c[nt], a_lo, bh0, bh1);
            }
        }
    }

    // epilogue: D layout rows {g, g+8}, cols tig*2 + {0,1}
#pragma unroll
    for (int nt = 0; nt < 8; nt++) {
        int col = wc * 64 + nt * 8 + tig * 2;
        if (v0) {
            *(float2*)(g_H + (size_t)r0 * DIM + col) = make_float2(c[nt][0], c[nt][1]);
            *(__half2*)(g_Hh + (size_t)r0 * DIM + col) =
                __floats2half2_rn(c[nt][0], c[nt][1]);
        }
        if (v1) {
            *(float2*)(g_H + (size_t)r1 * DIM + col) = make_float2(c[nt][2], c[nt][3]);
            *(__half2*)(g_Hh + (size_t)r1 * DIM + col) =
                __floats2half2_rn(c[nt][2], c[nt][3]);
        }
    }
}

// ---------------- K2: per-node attention scores ----------------
__global__ void score_kernel(const float* __restrict__ Al, const float* __restrict__ Ar) {
    int idx = blockIdx.x * blockDim.x + threadIdx.x;
    if (idx >= NN * HEADS) return;
    int n = idx >> 2;
    int h = idx & 3;
    const float4* Hp = (const float4*)(g_H + (size_t)n * DIM + h * ODIM);
    const float4* Ap = (const float4*)(Al + h * ODIM);
    const float4* Bp = (const float4*)(Ar + h * ODIM);
    float s = 0.f, t = 0.f;
#pragma unroll
    for (int i = 0; i < 8; i++) {
        float4 v = Hp[i];
        float4 a = Ap[i];
        float4 b = Bp[i];
        s += v.x * a.x + v.y * a.y + v.z * a.z + v.w * a.w;
        t += v.x * b.x + v.y * b.y + v.z * b.z + v.w * b.w;
    }
    g_Hs[idx] = s;
    g_Ht[idx] = t;
}

// ---------------- K3: histogram ----------------
__global__ void hist_kernel(const int* __restrict__ ei) {
    int e = blockIdx.x * blockDim.x + threadIdx.x;
    if (e < EE) atomicAdd(&g_cnt[ei[e]], 1);
}

// ---------------- K4: exclusive scan ----------------
__global__ __launch_bounds__(1024) void scan_kernel() {
    __shared__ int s[1024];
    int t = threadIdx.x;
    int beg = t * 49;
    int end2 = min(beg + 49, NN);
    int sum = 0;
    for (int i = beg; i < end2; i++) sum += g_cnt[i];
    s[t] = sum;
    __syncthreads();
    for (int off = 1; off < 1024; off <<= 1) {
        int v = 0;
        if (t >= off) v = s[t - off];
        __syncthreads();
        s[t] += v;
        __syncthreads();
    }
    int prefix = (t == 0) ? 0 : s[t - 1];
    for (int i = beg; i < end2; i++) {
        int c = g_cnt[i];
        g_off[i] = prefix;
        g_cur[i] = prefix;
        prefix += c;
    }
    if (t == 1023) g_off[NN] = EE;
}

// ---------------- K5: scatter into CSR + global max ----------------
__global__ void scatter_kernel(const int* __restrict__ ei) {
    int e = blockIdx.x * blockDim.x + threadIdx.x;
    float m = -1e30f;
    if (e < EE) {
        int src = ei[e];
        int tgt = ei[EE + e];
        int p = atomicAdd(&g_cur[src], 1);
        g_csr[p] = tgt;
        float4 hs = *(const float4*)(g_Hs + (size_t)src * 4);
        float4 ht = *(const float4*)(g_Ht + (size_t)tgt * 4);
        m = fmaxf(m, lrelu(hs.x + ht.x));
        m = fmaxf(m, lrelu(hs.y + ht.y));
        m = fmaxf(m, lrelu(hs.z + ht.z));
        m = fmaxf(m, lrelu(hs.w + ht.w));
    }
#pragma unroll
    for (int o = 16; o > 0; o >>= 1)
        m = fmaxf(m, __shfl_xor_sync(0xffffffffu, m, o));
    __shared__ float sm[8];
    int lane = threadIdx.x & 31, wid = threadIdx.x >> 5;
    if (lane == 0) sm[wid] = m;
    __syncthreads();
    if (wid == 0) {
        m = (lane < (blockDim.x >> 5)) ? sm[lane] : -1e30f;
#pragma unroll
        for (int o = 4; o > 0; o >>= 1)
            m = fmaxf(m, __shfl_xor_sync(0xffffffffu, m, o));
        if (lane == 0) atomicMax(&g_maxenc, enc_f(m));
    }
}

// ---------------- K6: fused denom + aggregation + ELU ----------------
__device__ __forceinline__ void agg_step(int j, int lane, int h,
                                         const int* s_tgt, const float* s_e,
                                         float4& acc) {
    int t = s_tgt[j];
    float ej = s_e[j * 4 + h];
    const __half2* hp = (const __half2*)(g_Hh + (size_t)t * DIM + lane * 4);
    __half2 a = hp[0], b = hp[1];
    float2 fa = __half22float2(a);
    float2 fb = __half22float2(b);
    acc.x = fmaf(ej, fa.x, acc.x);
    acc.y = fmaf(ej, fa.y, acc.y);
    acc.z = fmaf(ej, fb.x, acc.z);
    acc.w = fmaf(ej, fb.y, acc.w);
}

__global__ __launch_bounds__(WPB * 32) void agg_kernel(float* __restrict__ out) {
    __shared__ int   s_tgt[WPB][32];
    __shared__ float s_e[WPB][32 * 4];
    int wid  = threadIdx.x >> 5;
    int lane = threadIdx.x & 31;
    int node = blockIdx.x * WPB + wid;
    if (node >= NN) return;
    int h = lane >> 3;
    int start = g_off[node];
    int end   = g_off[node + 1];
    float gmax = dec_f(g_maxenc);
    float4 hs = *(const float4*)(g_Hs + (size_t)node * 4);

    float4 acc0 = make_float4(0.f, 0.f, 0.f, 0.f);
    float4 acc1 = make_float4(0.f, 0.f, 0.f, 0.f);
    float4 dsum = make_float4(0.f, 0.f, 0.f, 0.f);

    for (int base = start; base < end; base += 32) {
        int cnt = min(32, end - base);
        int tgt = 0;
        float4 e4 = make_float4(0.f, 0.f, 0.f, 0.f);
        if (lane < cnt) {
            tgt = g_csr[base + lane];
            float4 ht = *(const float4*)(g_Ht + (size_t)tgt * 4);
            e4.x = __expf(lrelu(hs.x + ht.x) - gmax);
            e4.y = __expf(lrelu(hs.y + ht.y) - gmax);
            e4.z = __expf(lrelu(hs.z + ht.z) - gmax);
            e4.w = __expf(lrelu(hs.w + ht.w) - gmax);
            dsum.x += e4.x; dsum.y += e4.y; dsum.z += e4.z; dsum.w += e4.w;
        }
        s_tgt[wid][lane] = tgt;
        *(float4*)&s_e[wid][lane * 4] = e4;
        __syncwarp();
        if (cnt == 32) {
#pragma unroll
            for (int j = 0; j < 32; j += 2) {
                agg_step(j,     lane, h, s_tgt[wid], s_e[wid], acc0);
                agg_step(j + 1, lane, h, s_tgt[wid], s_e[wid], acc1);
            }
        } else {
#pragma unroll 4
            for (int j = 0; j < cnt; j++)
                agg_step(j, lane, h, s_tgt[wid], s_e[wid], acc0);
        }
        __syncwarp();
    }

    float4 acc = make_float4(acc0.x + acc1.x, acc0.y + acc1.y,
                             acc0.z + acc1.z, acc0.w + acc1.w);
#pragma unroll
    for (int o = 16; o > 0; o >>= 1) {
        dsum.x += __shfl_xor_sync(0xffffffffu, dsum.x, o);
        dsum.y += __shfl_xor_sync(0xffffffffu, dsum.y, o);
        dsum.z += __shfl_xor_sync(0xffffffffu, dsum.z, o);
        dsum.w += __shfl_xor_sync(0xffffffffu, dsum.w, o);
    }
    float dh = (h == 0) ? dsum.x : (h == 1) ? dsum.y : (h == 2) ? dsum.z : dsum.w;
    float sc = 1.0f / (dh + 1e-8f);
    acc.x *= sc; acc.y *= sc; acc.z *= sc; acc.w *= sc;
    acc.x = acc.x > 0.f ? acc.x : expm1f(acc.x);
    acc.y = acc.y > 0.f ? acc.y : expm1f(acc.y);
    acc.z = acc.z > 0.f ? acc.z : expm1f(acc.z);
    acc.w = acc.w > 0.f ? acc.w : expm1f(acc.w);
    *(float4*)(out + (size_t)node * DIM + lane * 4) = acc;
}

extern "C" void kernel_launch(void* const* d_in, const int* in_sizes, int n_in,
                              void* d_out, int out_size) {
    const float* X  = (const float*)d_in[0];
    const int* EI   = (const int*)d_in[1];
    const float* W  = (const float*)d_in[2];
    const float* Al = (const float*)d_in[3];
    const float* Ar = (const float*)d_in[4];
    float* out = (float*)d_out;

    init_kernel<<<(NN + 255) / 256, 256>>>();
    gemm_tc<<<(NN + 63) / 64, 256>>>(X, W);
    score_kernel<<<(NN * HEADS + 255) / 256, 256>>>(Al, Ar);
    hist_kernel<<<(EE + 255) / 256, 256>>>(EI);
    scan_kernel<<<1, 1024>>>();
    scatter_kernel<<<(EE + 255) / 256, 256>>>(EI);
    agg_kernel<<<(NN + WPB - 1) / WPB, WPB * 32>>>(out);
}

// round 7
// speedup vs baseline: 1.2194x; 1.2194x over previous
#include <cuda_runtime.h>
#include <cuda_fp16.h>
#include <math.h>

#define NN 50000
#define EE 1600000
#define DIM 128
#define HEADS 4
#define ODIM 32
#define ALPHA 0.2f
#define WPB 8

// ---------------- device scratch ----------------
__device__ __align__(16) float  g_H[NN * DIM];     // fp32 features (scores path)
__device__ __align__(16) __half g_Hh[NN * DIM];    // fp16 features (gather path)
__device__ __align__(16) float  g_Hs[NN * HEADS];
__device__ __align__(16) float  g_Ht[NN * HEADS];
__device__ int g_cnt[NN];        // zero at load; re-zeroed by scan each run
__device__ int g_off[NN + 1];
__device__ int g_cur[NN];
__device__ int g_csr[EE];
__device__ unsigned g_maxh[8];   // enc(max Hs_h) [0..3], enc(max Ht_h) [4..7]

__device__ __forceinline__ unsigned enc_f(float f) {
    unsigned u = __float_as_uint(f);
    return (u & 0x80000000u) ? ~u : (u | 0x80000000u);
}
__device__ __forceinline__ float dec_f(unsigned u) {
    return (u & 0x80000000u) ? __uint_as_float(u ^ 0x80000000u)
                             : __uint_as_float(~u);
}
__device__ __forceinline__ float lrelu(float x) { return x > 0.f ? x : ALPHA * x; }

// ---------------- chain A, K1: SIMT GEMM  H = X @ W (+ fp16 copy, + max reset) ----------------
__global__ __launch_bounds__(256) void gemm_kernel(const float* __restrict__ X,
                                                   const float* __restrict__ W) {
    if (blockIdx.x == 0 && threadIdx.x < 8) g_maxh[threadIdx.x] = 0u;
    __shared__ __align__(16) float Xs[16][132];
    __shared__ __align__(16) float Ws[16][128];
    const int m0 = blockIdx.x * 128;
    const int tid = threadIdx.x;
    const int tx = tid & 15;
    const int ty = tid >> 4;
    float acc[8][8];
#pragma unroll
    for (int i = 0; i < 8; i++)
#pragma unroll
        for (int j = 0; j < 8; j++) acc[i][j] = 0.0f;

    for (int k0 = 0; k0 < DIM; k0 += 16) {
#pragma unroll
        for (int j = 0; j < 2; j++) {
            int s = tid * 2 + j;
            int m = s >> 2;
            int kk4 = (s & 3) * 4;
            float4 v = make_float4(0.f, 0.f, 0.f, 0.f);
            int gm = m0 + m;
            if (gm < NN) v = *(const float4*)(X + (size_t)gm * DIM + k0 + kk4);
            Xs[kk4 + 0][m] = v.x;
            Xs[kk4 + 1][m] = v.y;
            Xs[kk4 + 2][m] = v.z;
            Xs[kk4 + 3][m] = v.w;
            int wk = s >> 5;
            int wc = (s & 31) * 4;
            *(float4*)&Ws[wk][wc] = *(const float4*)(W + (size_t)(k0 + wk) * DIM + wc);
        }
        __syncthreads();
#pragma unroll
        for (int kk = 0; kk < 16; kk++) {
            float a[8], b[8];
            *(float4*)(a)     = *(float4*)&Xs[kk][ty * 8];
            *(float4*)(a + 4) = *(float4*)&Xs[kk][ty * 8 + 4];
            *(float4*)(b)     = *(float4*)&Ws[kk][tx * 8];
            *(float4*)(b + 4) = *(float4*)&Ws[kk][tx * 8 + 4];
#pragma unroll
            for (int i = 0; i < 8; i++)
#pragma unroll
                for (int j = 0; j < 8; j++) acc[i][j] = fmaf(a[i], b[j], acc[i][j]);
        }
        __syncthreads();
    }
#pragma unroll
    for (int i = 0; i < 8; i++) {
        int gm = m0 + ty * 8 + i;
        if (gm < NN) {
            float4 v0 = make_float4(acc[i][0], acc[i][1], acc[i][2], acc[i][3]);
            float4 v1 = make_float4(acc[i][4], acc[i][5], acc[i][6], acc[i][7]);
            *(float4*)(g_H + (size_t)gm * DIM + tx * 8)     = v0;
            *(float4*)(g_H + (size_t)gm * DIM + tx * 8 + 4) = v1;
            __half2 h0 = __float22half2_rn(make_float2(v0.x, v0.y));
            __half2 h1 = __float22half2_rn(make_float2(v0.z, v0.w));
            __half2 h2 = __float22half2_rn(make_float2(v1.x, v1.y));
            __half2 h3 = __float22half2_rn(make_float2(v1.z, v1.w));
            __half2* hp = (__half2*)(g_Hh + (size_t)gm * DIM + tx * 8);
            hp[0] = h0; hp[1] = h1; hp[2] = h2; hp[3] = h3;
        }
    }
}

// ---------------- chain A, K2: per-node scores + per-head maxes ----------------
__global__ __launch_bounds__(256) void score_kernel(const float* __restrict__ Al,
                                                    const float* __restrict__ Ar) {
    __shared__ unsigned sm8[8];
    int tid = threadIdx.x;
    if (tid < 8) sm8[tid] = 0u;
    __syncthreads();

    int idx = blockIdx.x * 256 + tid;
    bool valid = (idx < NN * HEADS);
    float s = -1e30f, t = -1e30f;
    if (valid) {
        int n = idx >> 2;
        int h = idx & 3;
        const float4* Hp = (const float4*)(g_H + (size_t)n * DIM + h * ODIM);
        const float4* Ap = (const float4*)(Al + h * ODIM);
        const float4* Bp = (const float4*)(Ar + h * ODIM);
        s = 0.f; t = 0.f;
#pragma unroll
        for (int i = 0; i < 8; i++) {
            float4 v = Hp[i];
            float4 a = Ap[i];
            float4 b = Bp[i];
            s += v.x * a.x + v.y * a.y + v.z * a.z + v.w * a.w;
            t += v.x * b.x + v.y * b.y + v.z * b.z + v.w * b.w;
        }
        g_Hs[idx] = s;
        g_Ht[idx] = t;
    }
    // reduce max over lanes with the same h (shfl offsets 4/8/16 preserve lane&3)
    float ms = s, mt = t;
#pragma unroll
    for (int o = 4; o <= 16; o <<= 1) {
        ms = fmaxf(ms, __shfl_xor_sync(0xffffffffu, ms, o));
        mt = fmaxf(mt, __shfl_xor_sync(0xffffffffu, mt, o));
    }
    int lane = tid & 31;
    if (lane < 4) {
        atomicMax(&sm8[lane],     enc_f(ms));
        atomicMax(&sm8[4 + lane], enc_f(mt));
    }
    __syncthreads();
    if (tid < 8) atomicMax(&g_maxh[tid], sm8[tid]);
}

// ---------------- chain B, K3: histogram ----------------
__global__ void hist_kernel(const int* __restrict__ ei) {
    int e = blockIdx.x * blockDim.x + threadIdx.x;
    if (e < EE) atomicAdd(&g_cnt[ei[e]], 1);
}

// ---------------- chain B, K4: exclusive scan (+ cnt re-zero) ----------------
__global__ __launch_bounds__(1024) void scan_kernel() {
    __shared__ int s[1024];
    int t = threadIdx.x;
    int beg = t * 49;
    int end2 = min(beg + 49, NN);
    int sum = 0;
    for (int i = beg; i < end2; i++) sum += g_cnt[i];
    s[t] = sum;
    __syncthreads();
    for (int off = 1; off < 1024; off <<= 1) {
        int v = 0;
        if (t >= off) v = s[t - off];
        __syncthreads();
        s[t] += v;
        __syncthreads();
    }
    int prefix = (t == 0) ? 0 : s[t - 1];
    for (int i = beg; i < end2; i++) {
        int c = g_cnt[i];
        g_off[i] = prefix;
        g_cur[i] = prefix;
        g_cnt[i] = 0;          // ready for next replay
        prefix += c;
    }
    if (t == 1023) g_off[NN] = EE;
}

// ---------------- chain B, K5: scatter edges into CSR ----------------
__global__ void scatter_kernel(const int* __restrict__ ei) {
    int e = blockIdx.x * blockDim.x + threadIdx.x;
    if (e < EE) {
        int src = ei[e];
        int tgt = ei[EE + e];
        int p = atomicAdd(&g_cur[src], 1);
        g_csr[p] = tgt;
    }
}

// ---------------- join, K6: fused softmax + aggregation + ELU ----------------
__device__ __forceinline__ void agg_step(int j, int lane, int h,
                                         const int* s_tgt, const float* s_e,
                                         float4& acc) {
    int t = s_tgt[j];
    float ej = s_e[j * 4 + h];
    const __half2* hp = (const __half2*)(g_Hh + (size_t)t * DIM + lane * 4);
    __half2 a = hp[0], b = hp[1];
    float2 fa = __half22float2(a);
    float2 fb = __half22float2(b);
    acc.x = fmaf(ej, fa.x, acc.x);
    acc.y = fmaf(ej, fa.y, acc.y);
    acc.z = fmaf(ej, fb.x, acc.z);
    acc.w = fmaf(ej, fb.y, acc.w);
}

__global__ __launch_bounds__(WPB * 32) void agg_kernel(float* __restrict__ out) {
    __shared__ int   s_tgt[WPB][32];
    __shared__ float s_e[WPB][32 * 4];
    int wid  = threadIdx.x >> 5;
    int lane = threadIdx.x & 31;
    int node = blockIdx.x * WPB + wid;
    if (node >= NN) return;
    int h = lane >> 3;
    int start = g_off[node];
    int end   = g_off[node + 1];
    float4 M4;
    M4.x = lrelu(dec_f(g_maxh[0]) + dec_f(g_maxh[4]));
    M4.y = lrelu(dec_f(g_maxh[1]) + dec_f(g_maxh[5]));
    M4.z = lrelu(dec_f(g_maxh[2]) + dec_f(g_maxh[6]));
    M4.w = lrelu(dec_f(g_maxh[3]) + dec_f(g_maxh[7]));
    float4 hs = *(const float4*)(g_Hs + (size_t)node * 4);

    float4 acc0 = make_float4(0.f, 0.f, 0.f, 0.f);
    float4 acc1 = make_float4(0.f, 0.f, 0.f, 0.f);
    float4 dsum = make_float4(0.f, 0.f, 0.f, 0.f);

    for (int base = start; base < end; base += 32) {
        int cnt = min(32, end - base);
        int tgt = 0;
        float4 e4 = make_float4(0.f, 0.f, 0.f, 0.f);
        if (lane < cnt) {
            tgt = g_csr[base + lane];
            float4 ht = *(const float4*)(g_Ht + (size_t)tgt * 4);
            e4.x = __expf(lrelu(hs.x + ht.x) - M4.x);
            e4.y = __expf(lrelu(hs.y + ht.y) - M4.y);
            e4.z = __expf(lrelu(hs.z + ht.z) - M4.z);
            e4.w = __expf(lrelu(hs.w + ht.w) - M4.w);
            dsum.x += e4.x; dsum.y += e4.y; dsum.z += e4.z; dsum.w += e4.w;
        }
        s_tgt[wid][lane] = tgt;
        *(float4*)&s_e[wid][lane * 4] = e4;
        __syncwarp();
        if (cnt == 32) {
#pragma unroll
            for (int j = 0; j < 32; j += 2) {
                agg_step(j,     lane, h, s_tgt[wid], s_e[wid], acc0);
                agg_step(j + 1, lane, h, s_tgt[wid], s_e[wid], acc1);
            }
        } else {
#pragma unroll 4
            for (int j = 0; j < cnt; j++)
                agg_step(j, lane, h, s_tgt[wid], s_e[wid], acc0);
        }
        __syncwarp();
    }

    float4 acc = make_float4(acc0.x + acc1.x, acc0.y + acc1.y,
                             acc0.z + acc1.z, acc0.w + acc1.w);
#pragma unroll
    for (int o = 16; o > 0; o >>= 1) {
        dsum.x += __shfl_xor_sync(0xffffffffu, dsum.x, o);
        dsum.y += __shfl_xor_sync(0xffffffffu, dsum.y, o);
        dsum.z += __shfl_xor_sync(0xffffffffu, dsum.z, o);
        dsum.w += __shfl_xor_sync(0xffffffffu, dsum.w, o);
    }
    float dh = (h == 0) ? dsum.x : (h == 1) ? dsum.y : (h == 2) ? dsum.z : dsum.w;
    float sc = 1.0f / (dh + 1e-8f);
    acc.x *= sc; acc.y *= sc; acc.z *= sc; acc.w *= sc;
    acc.x = acc.x > 0.f ? acc.x : expm1f(acc.x);
    acc.y = acc.y > 0.f ? acc.y : expm1f(acc.y);
    acc.z = acc.z > 0.f ? acc.z : expm1f(acc.z);
    acc.w = acc.w > 0.f ? acc.w : expm1f(acc.w);
    *(float4*)(out + (size_t)node * DIM + lane * 4) = acc;
}

extern "C" void kernel_launch(void* const* d_in, const int* in_sizes, int n_in,
                              void* d_out, int out_size) {
    const float* X  = (const float*)d_in[0];
    const int* EI   = (const int*)d_in[1];
    const float* W  = (const float*)d_in[2];
    const float* Al = (const float*)d_in[3];
    const float* Ar = (const float*)d_in[4];
    float* out = (float*)d_out;

    static cudaStream_t sA = nullptr, sB = nullptr;
    static cudaEvent_t evFork = nullptr, evA = nullptr, evB = nullptr;
    if (sA == nullptr) {
        cudaStreamCreateWithFlags(&sA, cudaStreamNonBlocking);
        cudaStreamCreateWithFlags(&sB, cudaStreamNonBlocking);
        cudaEventCreateWithFlags(&evFork, cudaEventDisableTiming);
        cudaEventCreateWithFlags(&evA, cudaEventDisableTiming);
        cudaEventCreateWithFlags(&evB, cudaEventDisableTiming);
    }

    // fork from the (captured) default stream
    cudaEventRecord(evFork, 0);
    cudaStreamWaitEvent(sA, evFork, 0);
    cudaStreamWaitEvent(sB, evFork, 0);

    // chain A: features + scores
    gemm_kernel<<<(NN + 127) / 128, 256, 0, sA>>>(X, W);
    score_kernel<<<(NN * HEADS + 255) / 256, 256, 0, sA>>>(Al, Ar);
    cudaEventRecord(evA, sA);

    // chain B: CSR build
    hist_kernel<<<(EE + 255) / 256, 256, 0, sB>>>(EI);
    scan_kernel<<<1, 1024, 0, sB>>>();
    scatter_kernel<<<(EE + 255) / 256, 256, 0, sB>>>(EI);
    cudaEventRecord(evB, sB);

    // join on default stream
    cudaStreamWaitEvent(0, evA, 0);
    cudaStreamWaitEvent(0, evB, 0);
    agg_kernel<<<(NN + WPB - 1) / WPB, WPB * 32>>>(out);
}

// round 8
// speedup vs baseline: 1.7997x; 1.4758x over previous
#include <cuda_runtime.h>
#include <cuda_fp16.h>
#include <math.h>

#define NN 50000
#define EE 1600000
#define DIM 128
#define HEADS 4
#define ODIM 32
#define ALPHA 0.2f
#define WPB 8
#define SCAN_B 512
#define NSCB ((NN + SCAN_B - 1) / SCAN_B)   // 98

// ---------------- device scratch ----------------
__device__ __align__(16) float  g_H[NN * DIM];
__device__ __align__(16) __half g_Hh[NN * DIM];
__device__ __align__(16) float  g_Hs[NN * HEADS];
__device__ __align__(16) float  g_Ht[NN * HEADS];
__device__ int g_cnt[NN];        // zero at load; re-zeroed by scan3
__device__ int g_off[NN + 1];
__device__ int g_cur[NN];
__device__ int g_csr[EE];
__device__ int g_part[NSCB];
__device__ int g_partoff[NSCB];
__device__ unsigned g_maxh[8];

__device__ __forceinline__ unsigned enc_f(float f) {
    unsigned u = __float_as_uint(f);
    return (u & 0x80000000u) ? ~u : (u | 0x80000000u);
}
__device__ __forceinline__ float dec_f(unsigned u) {
    return (u & 0x80000000u) ? __uint_as_float(u ^ 0x80000000u)
                             : __uint_as_float(~u);
}
__device__ __forceinline__ float lrelu(float x) { return x > 0.f ? x : ALPHA * x; }

// ---------------- chain A, K1: SIMT GEMM ----------------
__global__ __launch_bounds__(256) void gemm_kernel(const float* __restrict__ X,
                                                   const float* __restrict__ W) {
    if (blockIdx.x == 0 && threadIdx.x < 8) g_maxh[threadIdx.x] = 0u;
    __shared__ __align__(16) float Xs[16][132];
    __shared__ __align__(16) float Ws[16][128];
    const int m0 = blockIdx.x * 128;
    const int tid = threadIdx.x;
    const int tx = tid & 15;
    const int ty = tid >> 4;
    float acc[8][8];
#pragma unroll
    for (int i = 0; i < 8; i++)
#pragma unroll
        for (int j = 0; j < 8; j++) acc[i][j] = 0.0f;

    for (int k0 = 0; k0 < DIM; k0 += 16) {
#pragma unroll
        for (int j = 0; j < 2; j++) {
            int s = tid * 2 + j;
            int m = s >> 2;
            int kk4 = (s & 3) * 4;
            float4 v = make_float4(0.f, 0.f, 0.f, 0.f);
            int gm = m0 + m;
            if (gm < NN) v = *(const float4*)(X + (size_t)gm * DIM + k0 + kk4);
            Xs[kk4 + 0][m] = v.x;
            Xs[kk4 + 1][m] = v.y;
            Xs[kk4 + 2][m] = v.z;
            Xs[kk4 + 3][m] = v.w;
            int wk = s >> 5;
            int wc = (s & 31) * 4;
            *(float4*)&Ws[wk][wc] = *(const float4*)(W + (size_t)(k0 + wk) * DIM + wc);
        }
        __syncthreads();
#pragma unroll
        for (int kk = 0; kk < 16; kk++) {
            float a[8], b[8];
            *(float4*)(a)     = *(float4*)&Xs[kk][ty * 8];
            *(float4*)(a + 4) = *(float4*)&Xs[kk][ty * 8 + 4];
            *(float4*)(b)     = *(float4*)&Ws[kk][tx * 8];
            *(float4*)(b + 4) = *(float4*)&Ws[kk][tx * 8 + 4];
#pragma unroll
            for (int i = 0; i < 8; i++)
#pragma unroll
                for (int j = 0; j < 8; j++) acc[i][j] = fmaf(a[i], b[j], acc[i][j]);
        }
        __syncthreads();
    }
#pragma unroll
    for (int i = 0; i < 8; i++) {
        int gm = m0 + ty * 8 + i;
        if (gm < NN) {
            float4 v0 = make_float4(acc[i][0], acc[i][1], acc[i][2], acc[i][3]);
            float4 v1 = make_float4(acc[i][4], acc[i][5], acc[i][6], acc[i][7]);
            *(float4*)(g_H + (size_t)gm * DIM + tx * 8)     = v0;
            *(float4*)(g_H + (size_t)gm * DIM + tx * 8 + 4) = v1;
            __half2 h0 = __float22half2_rn(make_float2(v0.x, v0.y));
            __half2 h1 = __float22half2_rn(make_float2(v0.z, v0.w));
            __half2 h2 = __float22half2_rn(make_float2(v1.x, v1.y));
            __half2 h3 = __float22half2_rn(make_float2(v1.z, v1.w));
            __half2* hp = (__half2*)(g_Hh + (size_t)gm * DIM + tx * 8);
            hp[0] = h0; hp[1] = h1; hp[2] = h2; hp[3] = h3;
        }
    }
}

// ---------------- chain A, K2: scores + per-head maxes ----------------
__global__ __launch_bounds__(256) void score_kernel(const float* __restrict__ Al,
                                                    const float* __restrict__ Ar) {
    __shared__ unsigned sm8[8];
    int tid = threadIdx.x;
    if (tid < 8) sm8[tid] = 0u;
    __syncthreads();

    int idx = blockIdx.x * 256 + tid;
    float s = -1e30f, t = -1e30f;
    if (idx < NN * HEADS) {
        int n = idx >> 2;
        int h = idx & 3;
        const float4* Hp = (const float4*)(g_H + (size_t)n * DIM + h * ODIM);
        const float4* Ap = (const float4*)(Al + h * ODIM);
        const float4* Bp = (const float4*)(Ar + h * ODIM);
        s = 0.f; t = 0.f;
#pragma unroll
        for (int i = 0; i < 8; i++) {
            float4 v = Hp[i];
            float4 a = Ap[i];
            float4 b = Bp[i];
            s += v.x * a.x + v.y * a.y + v.z * a.z + v.w * a.w;
            t += v.x * b.x + v.y * b.y + v.z * b.z + v.w * b.w;
        }
        g_Hs[idx] = s;
        g_Ht[idx] = t;
    }
    float ms = s, mt = t;
#pragma unroll
    for (int o = 4; o <= 16; o <<= 1) {
        ms = fmaxf(ms, __shfl_xor_sync(0xffffffffu, ms, o));
        mt = fmaxf(mt, __shfl_xor_sync(0xffffffffu, mt, o));
    }
    int lane = tid & 31;
    if (lane < 4) {
        atomicMax(&sm8[lane],     enc_f(ms));
        atomicMax(&sm8[4 + lane], enc_f(mt));
    }
    __syncthreads();
    if (tid < 8) atomicMax(&g_maxh[tid], sm8[tid]);
}

// ---------------- chain B, K3: histogram ----------------
__global__ void hist_kernel(const int* __restrict__ ei) {
    int e = blockIdx.x * blockDim.x + threadIdx.x;
    if (e < EE) atomicAdd(&g_cnt[ei[e]], 1);
}

// ---------------- chain B, K4a: block partial sums ----------------
__global__ __launch_bounds__(SCAN_B) void scan1_kernel() {
    __shared__ int sw[SCAN_B / 32];
    int i = blockIdx.x * SCAN_B + threadIdx.x;
    int v = (i < NN) ? g_cnt[i] : 0;
#pragma unroll
    for (int o = 16; o > 0; o >>= 1) v += __shfl_xor_sync(0xffffffffu, v, o);
    int lane = threadIdx.x & 31, wid = threadIdx.x >> 5;
    if (lane == 0) sw[wid] = v;
    __syncthreads();
    if (wid == 0) {
        v = (lane < SCAN_B / 32) ? sw[lane] : 0;
#pragma unroll
        for (int o = 8; o > 0; o >>= 1) v += __shfl_xor_sync(0xffffffffu, v, o);
        if (lane == 0) g_part[blockIdx.x] = v;
    }
}

// ---------------- chain B, K4b: scan the 98 partials ----------------
__global__ __launch_bounds__(128) void scan2_kernel() {
    __shared__ int s[128];
    int t = threadIdx.x;
    s[t] = (t < NSCB) ? g_part[t] : 0;
    __syncthreads();
#pragma unroll
    for (int off = 1; off < 128; off <<= 1) {
        int v = (t >= off) ? s[t - off] : 0;
        __syncthreads();
        s[t] += v;
        __syncthreads();
    }
    if (t < NSCB) g_partoff[t] = (t == 0) ? 0 : s[t - 1];
}

// ---------------- chain B, K4c: in-block exclusive scan + write offsets ----------------
__global__ __launch_bounds__(SCAN_B) void scan3_kernel() {
    __shared__ int s[SCAN_B];
    int t = threadIdx.x;
    int i = blockIdx.x * SCAN_B + t;
    int v = (i < NN) ? g_cnt[i] : 0;
    s[t] = v;
    __syncthreads();
#pragma unroll
    for (int off = 1; off < SCAN_B; off <<= 1) {
        int u = (t >= off) ? s[t - off] : 0;
        __syncthreads();
        s[t] += u;
        __syncthreads();
    }
    if (i < NN) {
        int prefix = g_partoff[blockIdx.x] + s[t] - v;   // exclusive
        g_off[i] = prefix;
        g_cur[i] = prefix;
        g_cnt[i] = 0;
        if (i == NN - 1) g_off[NN] = EE;
    }
}

// ---------------- chain B, K5: scatter edges into CSR ----------------
__global__ void scatter_kernel(const int* __restrict__ ei) {
    int e = blockIdx.x * blockDim.x + threadIdx.x;
    if (e < EE) {
        int src = ei[e];
        int tgt = ei[EE + e];
        int p = atomicAdd(&g_cur[src], 1);
        g_csr[p] = tgt;
    }
}

// ---------------- join, K6: fused softmax + aggregation + ELU ----------------
__device__ __forceinline__ void agg_step(int j, int lane, int h,
                                         const int* s_tgt, const float* s_e,
                                         float4& acc) {
    int t = s_tgt[j];
    float ej = s_e[j * 4 + h];
    const __half2* hp = (const __half2*)(g_Hh + (size_t)t * DIM + lane * 4);
    __half2 a = hp[0], b = hp[1];
    float2 fa = __half22float2(a);
    float2 fb = __half22float2(b);
    acc.x = fmaf(ej, fa.x, acc.x);
    acc.y = fmaf(ej, fa.y, acc.y);
    acc.z = fmaf(ej, fb.x, acc.z);
    acc.w = fmaf(ej, fb.y, acc.w);
}

__global__ __launch_bounds__(WPB * 32) void agg_kernel(float* __restrict__ out) {
    __shared__ int   s_tgt[WPB][32];
    __shared__ float s_e[WPB][32 * 4];
    int wid  = threadIdx.x >> 5;
    int lane = threadIdx.x & 31;
    int node = blockIdx.x * WPB + wid;
    if (node >= NN) return;
    int h = lane >> 3;
    int start = g_off[node];
    int end   = g_off[node + 1];
    float4 M4;
    M4.x = lrelu(dec_f(g_maxh[0]) + dec_f(g_maxh[4]));
    M4.y = lrelu(dec_f(g_maxh[1]) + dec_f(g_maxh[5]));
    M4.z = lrelu(dec_f(g_maxh[2]) + dec_f(g_maxh[6]));
    M4.w = lrelu(dec_f(g_maxh[3]) + dec_f(g_maxh[7]));
    float4 hs = *(const float4*)(g_Hs + (size_t)node * 4);

    float4 acc0 = make_float4(0.f, 0.f, 0.f, 0.f);
    float4 acc1 = make_float4(0.f, 0.f, 0.f, 0.f);
    float4 dsum = make_float4(0.f, 0.f, 0.f, 0.f);

    for (int base = start; base < end; base += 32) {
        int cnt = min(32, end - base);
        int tgt = 0;
        float4 e4 = make_float4(0.f, 0.f, 0.f, 0.f);
        if (lane < cnt) {
            tgt = g_csr[base + lane];
            float4 ht = *(const float4*)(g_Ht + (size_t)tgt * 4);
            e4.x = __expf(lrelu(hs.x + ht.x) - M4.x);
            e4.y = __expf(lrelu(hs.y + ht.y) - M4.y);
            e4.z = __expf(lrelu(hs.z + ht.z) - M4.z);
            e4.w = __expf(lrelu(hs.w + ht.w) - M4.w);
            dsum.x += e4.x; dsum.y += e4.y; dsum.z += e4.z; dsum.w += e4.w;
        }
        s_tgt[wid][lane] = tgt;
        *(float4*)&s_e[wid][lane * 4] = e4;
        __syncwarp();
        if (cnt == 32) {
#pragma unroll
            for (int j = 0; j < 32; j += 2) {
                agg_step(j,     lane, h, s_tgt[wid], s_e[wid], acc0);
                agg_step(j + 1, lane, h, s_tgt[wid], s_e[wid], acc1);
            }
        } else {
#pragma unroll 4
            for (int j = 0; j < cnt; j++)
                agg_step(j, lane, h, s_tgt[wid], s_e[wid], acc0);
        }
        __syncwarp();
    }

    float4 acc = make_float4(acc0.x + acc1.x, acc0.y + acc1.y,
                             acc0.z + acc1.z, acc0.w + acc1.w);
#pragma unroll
    for (int o = 16; o > 0; o >>= 1) {
        dsum.x += __shfl_xor_sync(0xffffffffu, dsum.x, o);
        dsum.y += __shfl_xor_sync(0xffffffffu, dsum.y, o);
        dsum.z += __shfl_xor_sync(0xffffffffu, dsum.z, o);
        dsum.w += __shfl_xor_sync(0xffffffffu, dsum.w, o);
    }
    float dh = (h == 0) ? dsum.x : (h == 1) ? dsum.y : (h == 2) ? dsum.z : dsum.w;
    float sc = 1.0f / (dh + 1e-8f);
    acc.x *= sc; acc.y *= sc; acc.z *= sc; acc.w *= sc;
    acc.x = acc.x > 0.f ? acc.x : expm1f(acc.x);
    acc.y = acc.y > 0.f ? acc.y : expm1f(acc.y);
    acc.z = acc.z > 0.f ? acc.z : expm1f(acc.z);
    acc.w = acc.w > 0.f ? acc.w : expm1f(acc.w);
    *(float4*)(out + (size_t)node * DIM + lane * 4) = acc;
}

extern "C" void kernel_launch(void* const* d_in, const int* in_sizes, int n_in,
                              void* d_out, int out_size) {
    const float* X  = (const float*)d_in[0];
    const int* EI   = (const int*)d_in[1];
    const float* W  = (const float*)d_in[2];
    const float* Al = (const float*)d_in[3];
    const float* Ar = (const float*)d_in[4];
    float* out = (float*)d_out;

    static cudaStream_t sA = nullptr, sB = nullptr;
    static cudaEvent_t evFork = nullptr, evA = nullptr, evB = nullptr;
    if (sA == nullptr) {
        cudaStreamCreateWithFlags(&sA, cudaStreamNonBlocking);
        cudaStreamCreateWithFlags(&sB, cudaStreamNonBlocking);
        cudaEventCreateWithFlags(&evFork, cudaEventDisableTiming);
        cudaEventCreateWithFlags(&evA, cudaEventDisableTiming);
        cudaEventCreateWithFlags(&evB, cudaEventDisableTiming);
    }

    cudaEventRecord(evFork, 0);
    cudaStreamWaitEvent(sA, evFork, 0);
    cudaStreamWaitEvent(sB, evFork, 0);

    // chain A: features + scores
    gemm_kernel<<<(NN + 127) / 128, 256, 0, sA>>>(X, W);
    score_kernel<<<(NN * HEADS + 255) / 256, 256, 0, sA>>>(Al, Ar);
    cudaEventRecord(evA, sA);

    // chain B: CSR build
    hist_kernel<<<(EE + 255) / 256, 256, 0, sB>>>(EI);
    scan1_kernel<<<NSCB, SCAN_B, 0, sB>>>();
    scan2_kernel<<<1, 128, 0, sB>>>();
    scan3_kernel<<<NSCB, SCAN_B, 0, sB>>>();
    scatter_kernel<<<(EE + 255) / 256, 256, 0, sB>>>(EI);
    cudaEventRecord(evB, sB);

    cudaStreamWaitEvent(0, evA, 0);
    cudaStreamWaitEvent(0, evB, 0);
    agg_kernel<<<(NN + WPB - 1) / WPB, WPB * 32>>>(out);
}

// round 9
// speedup vs baseline: 2.0754x; 1.1532x over previous
#include <cuda_runtime.h>
#include <cuda_fp16.h>
#include <math.h>

#define NN 50000
#define EE 1600000
#define DIM 128
#define HEADS 4
#define ODIM 32
#define ALPHA 0.2f
#define WPB 8
#define SCAN_B 512
#define NSCB ((NN + SCAN_B - 1) / SCAN_B)   // 98

// ---------------- device scratch ----------------
__device__ __align__(16) __half g_Hh[NN * DIM];   // fp16 features (only copy of H)
__device__ __align__(16) float  g_Hs[NN * HEADS];
__device__ __align__(16) float  g_Ht[NN * HEADS];
__device__ int g_cnt[NN];        // zero at load; re-zeroed by scan3
__device__ int g_off[NN + 1];
__device__ int g_cur[NN];
__device__ int g_csr[EE];
__device__ int g_part[NSCB];
__device__ int g_partoff[NSCB];
__device__ unsigned g_maxh[8];   // enc(max Hs_h) [0..3], enc(max Ht_h) [4..7]

__device__ __forceinline__ unsigned enc_f(float f) {
    unsigned u = __float_as_uint(f);
    return (u & 0x80000000u) ? ~u : (u | 0x80000000u);
}
__device__ __forceinline__ float dec_f(unsigned u) {
    return (u & 0x80000000u) ? __uint_as_float(u ^ 0x80000000u)
                             : __uint_as_float(~u);
}
__device__ __forceinline__ float lrelu(float x) { return x > 0.f ? x : ALPHA * x; }

// ---------------- chain A, K1: SIMT GEMM + fused scores/maxes ----------------
__global__ __launch_bounds__(256) void gemm_kernel(const float* __restrict__ X,
                                                   const float* __restrict__ W,
                                                   const float* __restrict__ Al,
                                                   const float* __restrict__ Ar) {
    if (blockIdx.x == 0 && threadIdx.x < 8) g_maxh[threadIdx.x] = 0u;
    __shared__ __align__(16) float Xs[16][132];
    __shared__ __align__(16) float Ws[16][128];
    __shared__ unsigned sm8[8];
    const int m0 = blockIdx.x * 128;
    const int tid = threadIdx.x;
    const int tx = tid & 15;
    const int ty = tid >> 4;
    if (tid < 8) sm8[tid] = 0u;

    float acc[8][8];
#pragma unroll
    for (int i = 0; i < 8; i++)
#pragma unroll
        for (int j = 0; j < 8; j++) acc[i][j] = 0.0f;

    // per-thread attention vector segments (head = tx>>2, sub = tx&3)
    const int head = tx >> 2;
    const int sub  = tx & 3;
    float alv[8], arv[8];
    {
        const float4* ap = (const float4*)(Al + head * ODIM + sub * 8);
        const float4* bp = (const float4*)(Ar + head * ODIM + sub * 8);
        *(float4*)(alv)     = ap[0];
        *(float4*)(alv + 4) = ap[1];
        *(float4*)(arv)     = bp[0];
        *(float4*)(arv + 4) = bp[1];
    }

    for (int k0 = 0; k0 < DIM; k0 += 16) {
#pragma unroll
        for (int j = 0; j < 2; j++) {
            int s = tid * 2 + j;
            int m = s >> 2;
            int kk4 = (s & 3) * 4;
            float4 v = make_float4(0.f, 0.f, 0.f, 0.f);
            int gm = m0 + m;
            if (gm < NN) v = *(const float4*)(X + (size_t)gm * DIM + k0 + kk4);
            Xs[kk4 + 0][m] = v.x;
            Xs[kk4 + 1][m] = v.y;
            Xs[kk4 + 2][m] = v.z;
            Xs[kk4 + 3][m] = v.w;
            int wk = s >> 5;
            int wc = (s & 31) * 4;
            *(float4*)&Ws[wk][wc] = *(const float4*)(W + (size_t)(k0 + wk) * DIM + wc);
        }
        __syncthreads();
#pragma unroll
        for (int kk = 0; kk < 16; kk++) {
            float a[8], b[8];
            *(float4*)(a)     = *(float4*)&Xs[kk][ty * 8];
            *(float4*)(a + 4) = *(float4*)&Xs[kk][ty * 8 + 4];
            *(float4*)(b)     = *(float4*)&Ws[kk][tx * 8];
            *(float4*)(b + 4) = *(float4*)&Ws[kk][tx * 8 + 4];
#pragma unroll
            for (int i = 0; i < 8; i++)
#pragma unroll
                for (int j = 0; j < 8; j++) acc[i][j] = fmaf(a[i], b[j], acc[i][j]);
        }
        __syncthreads();
    }

    float mymax_s = -1e30f, mymax_t = -1e30f;
#pragma unroll
    for (int i = 0; i < 8; i++) {
        int gm = m0 + ty * 8 + i;
        if (gm < NN) {
            // fp16 feature store (only copy)
            __half2 h0 = __float22half2_rn(make_float2(acc[i][0], acc[i][1]));
            __half2 h1 = __float22half2_rn(make_float2(acc[i][2], acc[i][3]));
            __half2 h2 = __float22half2_rn(make_float2(acc[i][4], acc[i][5]));
            __half2 h3 = __float22half2_rn(make_float2(acc[i][6], acc[i][7]));
            __half2* hp = (__half2*)(g_Hh + (size_t)gm * DIM + tx * 8);
            hp[0] = h0; hp[1] = h1; hp[2] = h2; hp[3] = h3;
            // fused partial scores for this thread's 8 cols (head segment sub)
            float s = 0.f, t = 0.f;
#pragma unroll
            for (int c = 0; c < 8; c++) {
                s = fmaf(acc[i][c], alv[c], s);
                t = fmaf(acc[i][c], arv[c], t);
            }
            // reduce over the 4 lanes sharing this (row, head): lanes differ in sub (xor 1,2)
            s += __shfl_xor_sync(0xffffffffu, s, 1);
            t += __shfl_xor_sync(0xffffffffu, t, 1);
            s += __shfl_xor_sync(0xffffffffu, s, 2);
            t += __shfl_xor_sync(0xffffffffu, t, 2);
            if (sub == 0) {
                g_Hs[(size_t)gm * 4 + head] = s;
                g_Ht[(size_t)gm * 4 + head] = t;
                mymax_s = fmaxf(mymax_s, s);
                mymax_t = fmaxf(mymax_t, t);
            }
        }
    }
    if (sub == 0) {
        atomicMax(&sm8[head],     enc_f(mymax_s));
        atomicMax(&sm8[4 + head], enc_f(mymax_t));
    }
    __syncthreads();
    if (tid < 8) atomicMax(&g_maxh[tid], sm8[tid]);
}

// ---------------- chain B, K3: histogram ----------------
__global__ void hist_kernel(const int* __restrict__ ei) {
    int e = blockIdx.x * blockDim.x + threadIdx.x;
    if (e < EE) atomicAdd(&g_cnt[ei[e]], 1);
}

// ---------------- chain B, K4a: block partial sums ----------------
__global__ __launch_bounds__(SCAN_B) void scan1_kernel() {
    __shared__ int sw[SCAN_B / 32];
    int i = blockIdx.x * SCAN_B + threadIdx.x;
    int v = (i < NN) ? g_cnt[i] : 0;
#pragma unroll
    for (int o = 16; o > 0; o >>= 1) v += __shfl_xor_sync(0xffffffffu, v, o);
    int lane = threadIdx.x & 31, wid = threadIdx.x >> 5;
    if (lane == 0) sw[wid] = v;
    __syncthreads();
    if (wid == 0) {
        v = (lane < SCAN_B / 32) ? sw[lane] : 0;
#pragma unroll
        for (int o = 8; o > 0; o >>= 1) v += __shfl_xor_sync(0xffffffffu, v, o);
        if (lane == 0) g_part[blockIdx.x] = v;
    }
}

// ---------------- chain B, K4b: scan the 98 partials ----------------
__global__ __launch_bounds__(128) void scan2_kernel() {
    __shared__ int s[128];
    int t = threadIdx.x;
    s[t] = (t < NSCB) ? g_part[t] : 0;
    __syncthreads();
#pragma unroll
    for (int off = 1; off < 128; off <<= 1) {
        int v = (t >= off) ? s[t - off] : 0;
        __syncthreads();
        s[t] += v;
        __syncthreads();
    }
    if (t < NSCB) g_partoff[t] = (t == 0) ? 0 : s[t - 1];
}

// ---------------- chain B, K4c: in-block exclusive scan + write offsets ----------------
__global__ __launch_bounds__(SCAN_B) void scan3_kernel() {
    __shared__ int s[SCAN_B];
    int t = threadIdx.x;
    int i = blockIdx.x * SCAN_B + t;
    int v = (i < NN) ? g_cnt[i] : 0;
    s[t] = v;
    __syncthreads();
#pragma unroll
    for (int off = 1; off < SCAN_B; off <<= 1) {
        int u = (t >= off) ? s[t - off] : 0;
        __syncthreads();
        s[t] += u;
        __syncthreads();
    }
    if (i < NN) {
        int prefix = g_partoff[blockIdx.x] + s[t] - v;
        g_off[i] = prefix;
        g_cur[i] = prefix;
        g_cnt[i] = 0;
        if (i == NN - 1) g_off[NN] = EE;
    }
}

// ---------------- chain B, K5: scatter edges into CSR ----------------
__global__ void scatter_kernel(const int* __restrict__ ei) {
    int e = blockIdx.x * blockDim.x + threadIdx.x;
    if (e < EE) {
        int src = ei[e];
        int tgt = ei[EE + e];
        int p = atomicAdd(&g_cur[src], 1);
        g_csr[p] = tgt;
    }
}

// ---------------- join, K6: fused softmax + aggregation + ELU ----------------
__device__ __forceinline__ void agg_step(int j, int lane, int h,
                                         const int* s_tgt, const float* s_e,
                                         float4& acc) {
    int t = s_tgt[j];
    float ej = s_e[j * 4 + h];
    const __half2* hp = (const __half2*)(g_Hh + (size_t)t * DIM + lane * 4);
    __half2 a = hp[0], b = hp[1];
    float2 fa = __half22float2(a);
    float2 fb = __half22float2(b);
    acc.x = fmaf(ej, fa.x, acc.x);
    acc.y = fmaf(ej, fa.y, acc.y);
    acc.z = fmaf(ej, fb.x, acc.z);
    acc.w = fmaf(ej, fb.y, acc.w);
}

__global__ __launch_bounds__(WPB * 32) void agg_kernel(float* __restrict__ out) {
    __shared__ int   s_tgt[WPB][32];
    __shared__ float s_e[WPB][32 * 4];
    int wid  = threadIdx.x >> 5;
    int lane = threadIdx.x & 31;
    int node = blockIdx.x * WPB + wid;
    if (node >= NN) return;
    int h = lane >> 3;
    int start = g_off[node];
    int end   = g_off[node + 1];
    float4 M4;
    M4.x = lrelu(dec_f(g_maxh[0]) + dec_f(g_maxh[4]));
    M4.y = lrelu(dec_f(g_maxh[1]) + dec_f(g_maxh[5]));
    M4.z = lrelu(dec_f(g_maxh[2]) + dec_f(g_maxh[6]));
    M4.w = lrelu(dec_f(g_maxh[3]) + dec_f(g_maxh[7]));
    float4 hs = *(const float4*)(g_Hs + (size_t)node * 4);

    float4 acc0 = make_float4(0.f, 0.f, 0.f, 0.f);
    float4 acc1 = make_float4(0.f, 0.f, 0.f, 0.f);
    float4 acc2 = make_float4(0.f, 0.f, 0.f, 0.f);
    float4 acc3 = make_float4(0.f, 0.f, 0.f, 0.f);
    float4 dsum = make_float4(0.f, 0.f, 0.f, 0.f);

    for (int base = start; base < end; base += 32) {
        int cnt = min(32, end - base);
        int tgt = 0;
        float4 e4 = make_float4(0.f, 0.f, 0.f, 0.f);
        if (lane < cnt) {
            tgt = g_csr[base + lane];
            float4 ht = *(const float4*)(g_Ht + (size_t)tgt * 4);
            e4.x = __expf(lrelu(hs.x + ht.x) - M4.x);
            e4.y = __expf(lrelu(hs.y + ht.y) - M4.y);
            e4.z = __expf(lrelu(hs.z + ht.z) - M4.z);
            e4.w = __expf(lrelu(hs.w + ht.w) - M4.w);
            dsum.x += e4.x; dsum.y += e4.y; dsum.z += e4.z; dsum.w += e4.w;
        }
        s_tgt[wid][lane] = tgt;
        *(float4*)&s_e[wid][lane * 4] = e4;
        __syncwarp();
        if (cnt == 32) {
#pragma unroll
            for (int j = 0; j < 32; j += 4) {
                agg_step(j,     lane, h, s_tgt[wid], s_e[wid], acc0);
                agg_step(j + 1, lane, h, s_tgt[wid], s_e[wid], acc1);
                agg_step(j + 2, lane, h, s_tgt[wid], s_e[wid], acc2);
                agg_step(j + 3, lane, h, s_tgt[wid], s_e[wid], acc3);
            }
        } else {
#pragma unroll 4
            for (int j = 0; j < cnt; j++)
                agg_step(j, lane, h, s_tgt[wid], s_e[wid], acc0);
        }
        __syncwarp();
    }

    float4 acc = make_float4(acc0.x + acc1.x + acc2.x + acc3.x,
                             acc0.y + acc1.y + acc2.y + acc3.y,
                             acc0.z + acc1.z + acc2.z + acc3.z,
                             acc0.w + acc1.w + acc2.w + acc3.w);
#pragma unroll
    for (int o = 16; o > 0; o >>= 1) {
        dsum.x += __shfl_xor_sync(0xffffffffu, dsum.x, o);
        dsum.y += __shfl_xor_sync(0xffffffffu, dsum.y, o);
        dsum.z += __shfl_xor_sync(0xffffffffu, dsum.z, o);
        dsum.w += __shfl_xor_sync(0xffffffffu, dsum.w, o);
    }
    float dh = (h == 0) ? dsum.x : (h == 1) ? dsum.y : (h == 2) ? dsum.z : dsum.w;
    float sc = 1.0f / (dh + 1e-8f);
    acc.x *= sc; acc.y *= sc; acc.z *= sc; acc.w *= sc;
    acc.x = acc.x > 0.f ? acc.x : expm1f(acc.x);
    acc.y = acc.y > 0.f ? acc.y : expm1f(acc.y);
    acc.z = acc.z > 0.f ? acc.z : expm1f(acc.z);
    acc.w = acc.w > 0.f ? acc.w : expm1f(acc.w);
    *(float4*)(out + (size_t)node * DIM + lane * 4) = acc;
}

extern "C" void kernel_launch(void* const* d_in, const int* in_sizes, int n_in,
                              void* d_out, int out_size) {
    const float* X  = (const float*)d_in[0];
    const int* EI   = (const int*)d_in[1];
    const float* W  = (const float*)d_in[2];
    const float* Al = (const float*)d_in[3];
    const float* Ar = (const float*)d_in[4];
    float* out = (float*)d_out;

    static cudaStream_t sA = nullptr, sB = nullptr;
    static cudaEvent_t evFork = nullptr, evA = nullptr, evB = nullptr;
    if (sA == nullptr) {
        cudaStreamCreateWithFlags(&sA, cudaStreamNonBlocking);
        cudaStreamCreateWithFlags(&sB, cudaStreamNonBlocking);
        cudaEventCreateWithFlags(&evFork, cudaEventDisableTiming);
        cudaEventCreateWithFlags(&evA, cudaEventDisableTiming);
        cudaEventCreateWithFlags(&evB, cudaEventDisableTiming);
    }

    cudaEventRecord(evFork, 0);
    cudaStreamWaitEvent(sA, evFork, 0);
    cudaStreamWaitEvent(sB, evFork, 0);

    // chain A: features + fused scores
    gemm_kernel<<<(NN + 127) / 128, 256, 0, sA>>>(X, W, Al, Ar);
    cudaEventRecord(evA, sA);

    // chain B: CSR build
    hist_kernel<<<(EE + 255) / 256, 256, 0, sB>>>(EI);
    scan1_kernel<<<NSCB, SCAN_B, 0, sB>>>();
    scan2_kernel<<<1, 128, 0, sB>>>();
    scan3_kernel<<<NSCB, SCAN_B, 0, sB>>>();
    scatter_kernel<<<(EE + 255) / 256, 256, 0, sB>>>(EI);
    cudaEventRecord(evB, sB);

    cudaStreamWaitEvent(0, evA, 0);
    cudaStreamWaitEvent(0, evB, 0);
    agg_kernel<<<(NN + WPB - 1) / WPB, WPB * 32>>>(out);
}